// round 1
// baseline (speedup 1.0000x reference)
#include <cuda_runtime.h>
#include <math.h>

#define BB 16
#define AA 3
#define CC 80
#define HH 76
#define WW 76
#define TT 50
#define PLANE (HH*WW)          // 5776
#define NPLANES (BB*AA)        // 48 conf planes

__constant__ float c_anch[18] = {10.f,13.f,16.f,30.f,33.f,23.f,30.f,61.f,62.f,45.f,
                                 59.f,119.f,116.f,90.f,156.f,198.f,373.f,326.f};

__device__ float g_part[NPLANES];

__device__ __forceinline__ float sigf(float z) { return 1.f / (1.f + expf(-z)); }

// Kernel A: per-plane sigmoid reduction of the conf channel (channel a*85+4).
__global__ void conf_kernel(const float* __restrict__ in) {
    int plane = blockIdx.x;                 // 0..47
    int b = plane / AA, a = plane - b * AA;
    const float* p = in + (size_t)(b * 255 + a * 85 + 4) * PLANE;
    float s = 0.f;
    for (int i = threadIdx.x; i < PLANE; i += blockDim.x)
        s += sigf(p[i]);
    // warp + block reduce
    __shared__ float sm[32];
    for (int o = 16; o > 0; o >>= 1) s += __shfl_down_sync(0xffffffffu, s, o);
    int w = threadIdx.x >> 5, l = threadIdx.x & 31;
    if (l == 0) sm[w] = s;
    __syncthreads();
    if (w == 0) {
        s = (l < (blockDim.x >> 5)) ? sm[l] : 0.f;
        for (int o = 16; o > 0; o >>= 1) s += __shfl_down_sync(0xffffffffu, s, o);
        if (l == 0) g_part[plane] = s;
    }
}

// Kernel B: one block. Per-target anchor match + gathered losses + dedupe + final sum.
__global__ void target_kernel(const float* __restrict__ in,
                              const float* __restrict__ tgt,
                              float* __restrict__ out) {
    __shared__ int   cell[BB * TT];     // 800 flat cell ids (assigned) / unique negatives
    __shared__ float s_lxywh;
    __shared__ float s_lcls;
    __shared__ int   s_valid;
    __shared__ int   s_unique;

    int tid = threadIdx.x;
    if (tid == 0) { s_lxywh = 0.f; s_lcls = 0.f; s_valid = 0; s_unique = 0; }
    __syncthreads();

    const int NT = BB * TT;  // 800
    float lxywh = 0.f, lcls = 0.f;
    int mycell = -1 - tid;   // distinct negative => never matches in dedupe
    int assigned = 0;

    if (tid < NT) {
        int b = tid / TT;
        const float* t5 = tgt + b * (TT * 5) + (tid - b * TT) * 5;
        float tc = t5[0], tx = t5[1], ty = t5[2], tw = t5[3], th = t5[4];
        int valid = ((tc + tx + ty + tw + th) != 0.f);
        if (valid) atomicAdd(&s_valid, 1);

        // best of 9 anchors via shared-center IoU; argmax keeps first max
        float best = -1e30f; int bi = 0;
        #pragma unroll
        for (int k = 0; k < 9; k++) {
            float aw = c_anch[2 * k]     * (1.f / 608.f);
            float ah = c_anch[2 * k + 1] * (1.f / 608.f);
            float inter = fminf(tw, aw) * fminf(th, ah);
            float uni   = tw * th + aw * ah - inter;
            float iou   = inter / uni;
            if (iou > best) { best = iou; bi = k; }
        }
        assigned = valid && (bi < AA);

        if (assigned) {
            int a_n = bi;   // bi < AA here, so % AA is identity
            int gi = (int)(tx * (float)WW); gi = min(max(gi, 0), WW - 1);
            int gj = (int)(ty * (float)HH); gj = min(max(gj, 0), HH - 1);
            int pos = gj * WW + gi;
            mycell = ((b * AA + a_n) * HH + gj) * WW + gi;

            float aw_s = c_anch[2 * a_n], ah_s = c_anch[2 * a_n + 1];
            float tx_t = tx * (float)WW - (float)gi;
            float ty_t = ty * (float)HH - (float)gj;
            float tw_t = logf(tw * 608.f / aw_s);
            float th_t = logf(th * 608.f / ah_s);
            float scale = 2.f * ty * tw;   // faithful to reference quirk

            const float* cp = in + (size_t)(b * 255 + a_n * 85) * PLANE + pos;
            float px = sigf(cp[0]);
            float py = sigf(cp[PLANE]);
            float pw = cp[2 * (size_t)PLANE];
            float ph = cp[3 * (size_t)PLANE];
            lxywh = scale * (fabsf(px - tx_t) + fabsf(py - ty_t) +
                             fabsf(pw - tw_t) + fabsf(ph - th_t));

            int ci = (int)tc;
            const float* clsp = cp + 5 * (size_t)PLANE;
            float s = 0.f;
            #pragma unroll 4
            for (int c = 0; c < CC; c++) {
                float p = sigf(clsp[(size_t)c * PLANE]);
                s += (c == ci) ? -logf(p) : -log1pf(-p);
            }
            lcls = s;
        }
    }

    cell[min(tid, NT - 1)] = (tid < NT) ? mycell : cell[NT - 1]; // safe write
    if (tid < NT) cell[tid] = mycell;
    __syncthreads();

    // dedupe assigned cells: count only first occurrence (scatter with equal values)
    if (assigned) {
        int first = 1;
        for (int j = 0; j < tid; j++)
            if (cell[j] == mycell) { first = 0; break; }
        if (first) atomicAdd(&s_unique, 1);
    }
    if (lxywh != 0.f) atomicAdd(&s_lxywh, lxywh);
    if (lcls  != 0.f) atomicAdd(&s_lcls, lcls);
    __syncthreads();

    if (tid == 0) {
        float confsum = 0.f;
        #pragma unroll
        for (int i = 0; i < NPLANES; i++) confsum += g_part[i];
        float nt = fmaxf((float)s_valid, 1.f);
        // loss = (sum conf - N_unique) + (lx+ly+lw+lh)/num_truths + loss_cls
        out[0] = confsum - (float)s_unique + s_lxywh / nt + s_lcls;
    }
}

extern "C" void kernel_launch(void* const* d_in, const int* in_sizes, int n_in,
                              void* d_out, int out_size) {
    const float* in  = (const float*)d_in[0];   // [16, 255, 76, 76]
    const float* tgt = (const float*)d_in[1];   // [16, 250]
    float* out = (float*)d_out;
    conf_kernel<<<NPLANES, 256>>>(in);
    target_kernel<<<1, 832>>>(in, tgt, out);
}

// round 2
// speedup vs baseline: 5.9107x; 5.9107x over previous
#include <cuda_runtime.h>
#include <math.h>

#define BB 16
#define AA 3
#define CC 80
#define HH 76
#define WW 76
#define TT 50
#define PLANE (HH*WW)            // 5776
#define NPLANES (BB*AA)          // 48 conf planes
#define NT (BB*TT)               // 800 targets
#define CONF_BLOCKS NPLANES      // 48
#define TGT_BLOCKS 100           // 8 warps each -> 800 warps
#define NBITWORDS ((NPLANES*PLANE + 31)/32)   // 8664

__constant__ float c_anch[18] = {10.f,13.f,16.f,30.f,33.f,23.f,30.f,61.f,62.f,45.f,
                                 59.f,119.f,116.f,90.f,156.f,198.f,373.f,326.f};

__device__ float g_part[NPLANES];   // per-plane conf sums
__device__ float g_tl[NT];          // per-target xywh loss (already *scale)
__device__ float g_tc[NT];          // per-target cls loss
__device__ int   g_cell[NT];        // flat cell id, -1 if unassigned
__device__ int   g_valid[NT];       // 0/1

__device__ __forceinline__ float sigf(float z) { return 1.f / (1.f + expf(-z)); }

// ── Kernel 1: blocks 0..47 reduce conf planes; blocks 48..147 = 1 warp/target ──
__global__ void main_kernel(const float* __restrict__ in,
                            const float* __restrict__ tgt) {
    if (blockIdx.x < CONF_BLOCKS) {
        int plane = blockIdx.x;
        int b = plane / AA, a = plane - b * AA;
        const float4* p = (const float4*)(in + (size_t)(b * 255 + a * 85 + 4) * PLANE);
        float s = 0.f;
        for (int i = threadIdx.x; i < PLANE / 4; i += blockDim.x) {
            float4 v = p[i];
            s += sigf(v.x) + sigf(v.y) + sigf(v.z) + sigf(v.w);
        }
        __shared__ float sm[8];
        for (int o = 16; o > 0; o >>= 1) s += __shfl_down_sync(0xffffffffu, s, o);
        int w = threadIdx.x >> 5, l = threadIdx.x & 31;
        if (l == 0) sm[w] = s;
        __syncthreads();
        if (w == 0) {
            s = (l < (blockDim.x >> 5)) ? sm[l] : 0.f;
            for (int o = 4; o > 0; o >>= 1) s += __shfl_down_sync(0xffffffffu, s, o);
            if (l == 0) g_part[plane] = s;
        }
        return;
    }

    // target phase: one warp per target
    int w = threadIdx.x >> 5, l = threadIdx.x & 31;
    int t = (blockIdx.x - CONF_BLOCKS) * 8 + w;
    if (t >= NT) return;

    int b = t / TT;
    const float* t5 = tgt + b * (TT * 5) + (t - b * TT) * 5;
    float tc = t5[0], tx = t5[1], ty = t5[2], tw = t5[3], th = t5[4];
    int valid = ((tc + tx + ty + tw + th) != 0.f);

    // best of 9 anchors (shared-center IoU), first-max argmax
    float best = -1e30f; int bi = 0;
    #pragma unroll
    for (int k = 0; k < 9; k++) {
        float aw = c_anch[2 * k]     * (1.f / 608.f);
        float ah = c_anch[2 * k + 1] * (1.f / 608.f);
        float inter = fminf(tw, aw) * fminf(th, ah);
        float uni   = tw * th + aw * ah - inter;
        float iou   = inter / uni;
        if (iou > best) { best = iou; bi = k; }
    }
    int assigned = valid && (bi < AA);

    float acc_xy = 0.f, acc_cls = 0.f;
    int mycell = -1;

    if (assigned) {
        int a_n = bi;
        int gi = (int)(tx * (float)WW); gi = min(max(gi, 0), WW - 1);
        int gj = (int)(ty * (float)HH); gj = min(max(gj, 0), HH - 1);
        int pos = gj * WW + gi;
        mycell = ((b * AA + a_n) * HH + gj) * WW + gi;

        float aw_s = c_anch[2 * a_n], ah_s = c_anch[2 * a_n + 1];
        float tx_t = tx * (float)WW - (float)gi;
        float ty_t = ty * (float)HH - (float)gj;
        float tw_t = logf(tw * 608.f / aw_s);
        float th_t = logf(th * 608.f / ah_s);
        float scale = 2.f * ty * tw;      // faithful to reference quirk
        int ci = (int)tc;

        const float* cp = in + (size_t)(b * 255 + a_n * 85) * PLANE + pos;

        // lanes split the 85 channels (skip conf ch 4)
        #pragma unroll
        for (int r = 0; r < 3; r++) {
            int ch = l + 32 * r;
            if (ch < 85 && ch != 4) {
                float v = cp[(size_t)ch * PLANE];
                if (ch == 0)      acc_xy += scale * fabsf(sigf(v) - tx_t);
                else if (ch == 1) acc_xy += scale * fabsf(sigf(v) - ty_t);
                else if (ch == 2) acc_xy += scale * fabsf(v - tw_t);
                else if (ch == 3) acc_xy += scale * fabsf(v - th_t);
                else {
                    int c = ch - 5;
                    float p = sigf(v);
                    acc_cls += (c == ci) ? -logf(p) : -log1pf(-p);
                }
            }
        }
        for (int o = 16; o > 0; o >>= 1) {
            acc_xy  += __shfl_down_sync(0xffffffffu, acc_xy, o);
            acc_cls += __shfl_down_sync(0xffffffffu, acc_cls, o);
        }
    }
    if (l == 0) {
        g_tl[t] = acc_xy;
        g_tc[t] = acc_cls;
        g_cell[t] = mycell;
        g_valid[t] = valid;
    }
}

// ── Kernel 2: bitmap dedupe + final sums ──
__global__ void finish_kernel(float* __restrict__ out) {
    __shared__ unsigned bm[NBITWORDS];
    __shared__ float s_lxywh, s_lcls, s_conf;
    __shared__ int s_valid, s_unique;
    int tid = threadIdx.x;
    if (tid == 0) { s_lxywh = 0.f; s_lcls = 0.f; s_conf = 0.f; s_valid = 0; s_unique = 0; }
    for (int i = tid; i < NBITWORDS; i += blockDim.x) bm[i] = 0u;
    __syncthreads();

    // warp-local partial sums to cut shared atomics
    float lx = 0.f, lc = 0.f, cf = 0.f;
    int va = 0, un = 0;
    if (tid < NT) {
        lx = g_tl[tid];
        lc = g_tc[tid];
        va = g_valid[tid];
        int cell = g_cell[tid];
        if (cell >= 0) {
            unsigned mask = 1u << (cell & 31);
            unsigned old = atomicOr(&bm[cell >> 5], mask);
            if (!(old & mask)) un = 1;
        }
    }
    if (tid < NPLANES) cf = g_part[tid];

    for (int o = 16; o > 0; o >>= 1) {
        lx += __shfl_down_sync(0xffffffffu, lx, o);
        lc += __shfl_down_sync(0xffffffffu, lc, o);
        cf += __shfl_down_sync(0xffffffffu, cf, o);
        va += __shfl_down_sync(0xffffffffu, va, o);
        un += __shfl_down_sync(0xffffffffu, un, o);
    }
    if ((tid & 31) == 0) {
        if (lx != 0.f) atomicAdd(&s_lxywh, lx);
        if (lc != 0.f) atomicAdd(&s_lcls, lc);
        if (cf != 0.f) atomicAdd(&s_conf, cf);
        if (va) atomicAdd(&s_valid, va);
        if (un) atomicAdd(&s_unique, un);
    }
    __syncthreads();

    if (tid == 0) {
        float nt = fmaxf((float)s_valid, 1.f);
        out[0] = s_conf - (float)s_unique + s_lxywh / nt + s_lcls;
    }
}

extern "C" void kernel_launch(void* const* d_in, const int* in_sizes, int n_in,
                              void* d_out, int out_size) {
    const float* in  = (const float*)d_in[0];   // [16, 255, 76, 76]
    const float* tgt = (const float*)d_in[1];   // [16, 250]
    float* out = (float*)d_out;
    main_kernel<<<CONF_BLOCKS + TGT_BLOCKS, 256>>>(in, tgt);
    finish_kernel<<<1, 1024>>>(out);
}